// round 4
// baseline (speedup 1.0000x reference)
#include <cuda_runtime.h>
#include <cuda_bf16.h>

// x:    [B=64, C=64, S=8192] float32
// mask: [B=64, S=8192] int32
// out:  patches [64, 512, 1024] float32  followed by  padding_mask [64, 512] float32
//
// patches[b, p, c*16 + j] = x[b, c, p*16 + j]   (stride == patch -> pure permutation)
// padding_mask[b, p] = (sum(mask[b, p*16 : p*16+16]) >= 8) ? 1.0f : 0.0f
//
// Persistent single-wave kernel: 1184 blocks (148 SMs x 8 resident) grid-stride
// over 8320 chunks (8192 permute chunks of 1024 float4 each + 128 mask chunks).
// Removes the 7-wave transition/tail cost seen in R3 (grid=8320, 7.03 waves).
// Permute chunks keep ILP=4 independent LDG.128 per thread.

#define B       64
#define C       64
#define S       8192
#define NP      512                       // n_patches
#define CP      1024                      // C * PATCH
#define TOTAL_OUT_F4     (B * NP * CP / 4)       // 8388608
#define F4_PER_CHUNK     1024                    // 256 threads x 4
#define PERMUTE_CHUNKS   (TOTAL_OUT_F4 / F4_PER_CHUNK)  // 8192
#define MASK_CHUNKS      128                     // 128 x 256 = 32768 = B*NP
#define TOTAL_CHUNKS     (PERMUTE_CHUNKS + MASK_CHUNKS) // 8320
#define GRID             1184                    // 148 SMs x 8 resident blocks

__device__ __forceinline__ int src_of(int i) {
    // output float4 index -> source float4 index in x
    int b  = i >> 17;                     // / 131072 (f4 per batch)
    int r  = i & ((NP * CP / 4) - 1);
    int p  = r >> 8;                      // / 256
    int r2 = r & 255;
    int c  = r2 >> 2;
    int j4 = r2 & 3;
    return ((b << 6) + c) * (S / 4) + (p << 2) + j4;
}

__global__ void __launch_bounds__(256)
fused_patch_kernel(const float4* __restrict__ x4,
                   const int4* __restrict__ m4,
                   float4* __restrict__ out4,
                   float* __restrict__ pm) {
    for (int blk = blockIdx.x; blk < TOTAL_CHUNKS; blk += GRID) {
        if (blk < PERMUTE_CHUNKS) {
            // ---- permute chunk: 1024 float4, ILP=4 per thread ----
            int base = blk * F4_PER_CHUNK + threadIdx.x;
            float4 v[4];
            #pragma unroll
            for (int k = 0; k < 4; k++)
                v[k] = x4[src_of(base + k * 256)];
            #pragma unroll
            for (int k = 0; k < 4; k++)
                out4[base + k * 256] = v[k];
        } else {
            // ---- mask chunk: 256 (b,p) cells, exact coverage ----
            int t = (blk - PERMUTE_CHUNKS) * 256 + threadIdx.x;
            int b = t >> 9;               // / 512
            int p = t & (NP - 1);
            int mbase = (b * S + p * 16) >> 2;
            int s = 0;
            #pragma unroll
            for (int k = 0; k < 4; k++) {
                int4 m = m4[mbase + k];
                s += m.x + m.y + m.z + m.w;
            }
            pm[t] = (s >= 8) ? 1.0f : 0.0f;
        }
    }
}

extern "C" void kernel_launch(void* const* d_in, const int* in_sizes, int n_in,
                              void* d_out, int out_size) {
    const float4* x4 = (const float4*)d_in[0];
    const int4*   m4 = (const int4*)d_in[1];
    float* out = (float*)d_out;
    float* pm  = out + (size_t)B * NP * CP;

    fused_patch_kernel<<<GRID, 256>>>(x4, m4, (float4*)out, pm);
}

// round 5
// speedup vs baseline: 1.1051x; 1.1051x over previous
#include <cuda_runtime.h>
#include <cuda_bf16.h>

// x:    [B=64, C=64, S=8192] float32
// mask: [B=64, S=8192] int32
// out:  patches [64, 512, 1024] float32  followed by  padding_mask [64, 512] float32
//
// patches[b, p, c*16 + j] = x[b, c, p*16 + j]   (stride == patch -> pure permutation)
// padding_mask[b, p] = (sum(mask[b, p*16 : p*16+16]) >= 8) ? 1.0f : 0.0f
//
// R3 flat-grid config (best: 36.0us kernel) + streaming cache hints:
// x reads and patch stores have zero reuse -> __ldcs/__stcs (evict-first)
// to keep L2 from thrashing and improve HBM streaming efficiency.
// Persistent variant (R4) regressed -- HW work-steal already hides waves.

#define B       64
#define C       64
#define S       8192
#define NP      512                       // n_patches
#define CP      1024                      // C * PATCH
#define TOTAL_OUT_F4     (B * NP * CP / 4)       // 8388608
#define F4_PER_BLOCK     1024                    // 256 threads x 4
#define PERMUTE_BLOCKS   (TOTAL_OUT_F4 / F4_PER_BLOCK)  // 8192
#define MASK_THREADS     (B * NP)                // 32768
#define MASK_BLOCKS      ((MASK_THREADS + 255) / 256)   // 128

__device__ __forceinline__ int src_of(int i) {
    // output float4 index -> source float4 index in x
    int b  = i >> 17;                     // / 131072 (f4 per batch)
    int r  = i & ((NP * CP / 4) - 1);
    int p  = r >> 8;                      // / 256
    int r2 = r & 255;
    int c  = r2 >> 2;
    int j4 = r2 & 3;
    return ((b << 6) + c) * (S / 4) + (p << 2) + j4;
}

__global__ void __launch_bounds__(256)
fused_patch_kernel(const float4* __restrict__ x4,
                   const int4* __restrict__ m4,
                   float4* __restrict__ out4,
                   float* __restrict__ pm) {
    int blk = blockIdx.x;
    if (blk < PERMUTE_BLOCKS) {
        // ---- permute: 4 independent streaming LDG.128 then 4 streaming STG.128 ----
        int base = blk * F4_PER_BLOCK + threadIdx.x;
        float4 v[4];
        #pragma unroll
        for (int k = 0; k < 4; k++)
            v[k] = __ldcs(&x4[src_of(base + k * 256)]);
        #pragma unroll
        for (int k = 0; k < 4; k++)
            __stcs(&out4[base + k * 256], v[k]);
    } else {
        // ---- mask: one (b,p) per thread ----
        int t = (blk - PERMUTE_BLOCKS) * 256 + threadIdx.x;
        if (t >= MASK_THREADS) return;
        int b = t >> 9;                   // / 512
        int p = t & (NP - 1);
        int mbase = (b * S + p * 16) >> 2;
        int s = 0;
        #pragma unroll
        for (int k = 0; k < 4; k++) {
            int4 m = __ldcs(&m4[mbase + k]);
            s += m.x + m.y + m.z + m.w;
        }
        pm[t] = (s >= 8) ? 1.0f : 0.0f;
    }
}

extern "C" void kernel_launch(void* const* d_in, const int* in_sizes, int n_in,
                              void* d_out, int out_size) {
    const float4* x4 = (const float4*)d_in[0];
    const int4*   m4 = (const int4*)d_in[1];
    float* out = (float*)d_out;
    float* pm  = out + (size_t)B * NP * CP;

    fused_patch_kernel<<<PERMUTE_BLOCKS + MASK_BLOCKS, 256>>>(
        x4, m4, (float4*)out, pm);
}

// round 9
// speedup vs baseline: 1.1441x; 1.0353x over previous
#include <cuda_runtime.h>
#include <cuda_bf16.h>

// x:    [B=64, C=64, S=8192] float32
// mask: [B=64, S=8192] int32
// out:  patches [64, 512, 1024] float32  followed by  padding_mask [64, 512] float32
//
// patches[b, p, c*16 + j] = x[b, c, p*16 + j]   (stride == patch -> pure permutation)
// padding_mask[b, p] = (sum(mask[b, p*16 : p*16+16]) >= 8) ? 1.0f : 0.0f
//
// R3 flat-grid config (best class: 36.0us kernel, ~92% of HBM spec combined),
// with the 128 latency-bound mask blocks moved to the FRONT of the grid so
// their long-scoreboard latency hides under the 8192 streaming permute blocks
// instead of forming a lone partial-wave tail. cs-hints dropped (R5: neutral).

#define B       64
#define C       64
#define S       8192
#define NP      512                       // n_patches
#define CP      1024                      // C * PATCH
#define TOTAL_OUT_F4     (B * NP * CP / 4)       // 8388608
#define F4_PER_BLOCK     1024                    // 256 threads x 4
#define PERMUTE_BLOCKS   (TOTAL_OUT_F4 / F4_PER_BLOCK)  // 8192
#define MASK_THREADS     (B * NP)                // 32768
#define MASK_BLOCKS      ((MASK_THREADS + 255) / 256)   // 128

__device__ __forceinline__ int src_of(int i) {
    // output float4 index -> source float4 index in x
    int b  = i >> 17;                     // / 131072 (f4 per batch)
    int r  = i & ((NP * CP / 4) - 1);
    int p  = r >> 8;                      // / 256
    int r2 = r & 255;
    int c  = r2 >> 2;
    int j4 = r2 & 3;
    return ((b << 6) + c) * (S / 4) + (p << 2) + j4;
}

__global__ void __launch_bounds__(256)
fused_patch_kernel(const float4* __restrict__ x4,
                   const int4* __restrict__ m4,
                   float4* __restrict__ out4,
                   float* __restrict__ pm) {
    int blk = blockIdx.x;
    if (blk >= MASK_BLOCKS) {
        // ---- permute: 4 independent LDG.128 then 4 STG.128, fully coalesced ----
        int base = (blk - MASK_BLOCKS) * F4_PER_BLOCK + threadIdx.x;
        float4 v[4];
        #pragma unroll
        for (int k = 0; k < 4; k++)
            v[k] = x4[src_of(base + k * 256)];
        #pragma unroll
        for (int k = 0; k < 4; k++)
            out4[base + k * 256] = v[k];
    } else {
        // ---- mask: one (b,p) per thread; scheduled first, hides under permute ----
        int t = blk * 256 + threadIdx.x;
        int b = t >> 9;                   // / 512
        int p = t & (NP - 1);
        int mbase = (b * S + p * 16) >> 2;
        int s = 0;
        #pragma unroll
        for (int k = 0; k < 4; k++) {
            int4 m = m4[mbase + k];
            s += m.x + m.y + m.z + m.w;
        }
        pm[t] = (s >= 8) ? 1.0f : 0.0f;
    }
}

extern "C" void kernel_launch(void* const* d_in, const int* in_sizes, int n_in,
                              void* d_out, int out_size) {
    const float4* x4 = (const float4*)d_in[0];
    const int4*   m4 = (const int4*)d_in[1];
    float* out = (float*)d_out;
    float* pm  = out + (size_t)B * NP * CP;

    fused_patch_kernel<<<MASK_BLOCKS + PERMUTE_BLOCKS, 256>>>(
        x4, m4, (float4*)out, pm);
}